// round 1
// baseline (speedup 1.0000x reference)
#include <cuda_runtime.h>
#include <math.h>

#define T_LEN 8192
#define D_SIG 128
#define RADIUS 63
#define NTAPS 127              // x in [-63, 63]
#define CONV_BLOCKS 64         // 64 * 128 = 8192 outputs
#define INV_SQRT_2PI 0.39894228f
#define NOISE_SIGMA 0.01f

__device__ float g_G[NTAPS];
__device__ float g_psedu[T_LEN];
__device__ float g_pmin[CONV_BLOCKS];
__device__ float g_pmax[CONV_BLOCKS];

__device__ __forceinline__ float warp_sum(float v) {
    #pragma unroll
    for (int o = 16; o > 0; o >>= 1) v += __shfl_xor_sync(0xffffffffu, v, o);
    return v;
}
__device__ __forceinline__ float warp_max(float v) {
    #pragma unroll
    for (int o = 16; o > 0; o >>= 1) v = fmaxf(v, __shfl_xor_sync(0xffffffffu, v, o));
    return v;
}
__device__ __forceinline__ float warp_min(float v) {
    #pragma unroll
    for (int o = 16; o > 0; o >>= 1) v = fminf(v, __shfl_xor_sync(0xffffffffu, v, o));
    return v;
}

// ---------------------------------------------------------------------------
// Kernel 1: build the combined Gaussian kernel table G[x], x = blockIdx - 63.
// Grid: NTAPS blocks x 128 threads. Thread d handles sigma_d; softmax over the
// 128 weights is recomputed redundantly per block (cheap).
// ---------------------------------------------------------------------------
__global__ void k_gtable(const float* __restrict__ weight,
                         const float* __restrict__ sigma_min,
                         const float* __restrict__ sigma_max) {
    __shared__ float sred[4];
    const int d   = threadIdx.x;       // 0..127
    const int wid = d >> 5;
    const int lid = d & 31;

    float w = weight[d];

    // block max of w
    float m = warp_max(w);
    if (lid == 0) sred[wid] = m;
    __syncthreads();
    float bm = fmaxf(fmaxf(sred[0], sred[1]), fmaxf(sred[2], sred[3]));
    __syncthreads();

    // block sum of exp(w - max)
    float e = expf(w - bm);
    float s = warp_sum(e);
    if (lid == 0) sred[wid] = s;
    __syncthreads();
    float bs = sred[0] + sred[1] + sred[2] + sred[3];
    __syncthreads();

    float p = e / bs;  // softmax weight for sigma d

    float smn = sigma_min[0];
    float smx = sigma_max[0];
    float sig = fabsf(smn + (float)d * (smx - smn) / 127.0f);

    float x = (float)blockIdx.x - 63.0f;
    float term = p * (INV_SQRT_2PI / sig) * expf(-(x * x) / (2.0f * sig * sig));

    float tsum = warp_sum(term);
    if (lid == 0) sred[wid] = tsum;
    __syncthreads();
    if (d == 0) g_G[blockIdx.x] = sred[0] + sred[1] + sred[2] + sred[3];
}

// ---------------------------------------------------------------------------
// Kernel 2: truncated convolution + noise, store psedu, per-block min/max.
// psedu[t] = sum_{x=-63}^{63} G(x) * mask[t-1-x] + 0.01*noise[t]
// Grid: 64 blocks x 128 threads, one output element per thread.
// ---------------------------------------------------------------------------
__global__ void k_conv(const float* __restrict__ X,
                       const float* __restrict__ noise) {
    __shared__ float sG[NTAPS];
    __shared__ float sM[256];   // mask window [base-64, base+191]
    __shared__ float smn4[4], smx4[4];

    const int tid  = threadIdx.x;
    const int base = blockIdx.x * 128;

    if (tid < NTAPS) sG[tid] = g_G[tid];

    #pragma unroll
    for (int i = tid; i < 256; i += 128) {
        int gi = base - 64 + i;
        float v = 0.0f;
        if (gi >= 0 && gi < T_LEN) v = (X[gi] > 0.5f) ? 1.0f : 0.0f;
        sM[i] = v;
    }
    __syncthreads();

    // mask index t-1-x, smem offset = tid + 63 - x = tid + 126 - k  (x = k-63)
    float acc = 0.0f;
    #pragma unroll
    for (int k = 0; k < NTAPS; ++k)
        acc = fmaf(sG[k], sM[tid + 126 - k], acc);

    const int t = base + tid;
    acc += NOISE_SIGMA * noise[t];
    g_psedu[t] = acc;

    float mn = warp_min(acc);
    float mx = warp_max(acc);
    if ((tid & 31) == 0) { smn4[tid >> 5] = mn; smx4[tid >> 5] = mx; }
    __syncthreads();
    if (tid == 0) {
        g_pmin[blockIdx.x] = fminf(fminf(smn4[0], smn4[1]), fminf(smn4[2], smn4[3]));
        g_pmax[blockIdx.x] = fmaxf(fmaxf(smx4[0], smx4[1]), fmaxf(smx4[2], smx4[3]));
    }
}

// ---------------------------------------------------------------------------
// Kernel 3: every block redundantly reduces the 64 partial min/max values,
// then normalizes its 128 outputs.
// ---------------------------------------------------------------------------
__global__ void k_norm(float* __restrict__ out) {
    __shared__ float tlo[4], thi[4];
    const int tid = threadIdx.x;

    float lo = INFINITY, hi = -INFINITY;
    if (tid < CONV_BLOCKS) { lo = g_pmin[tid]; hi = g_pmax[tid]; }
    lo = warp_min(lo);
    hi = warp_max(hi);
    if ((tid & 31) == 0) { tlo[tid >> 5] = lo; thi[tid >> 5] = hi; }
    __syncthreads();
    lo = fminf(fminf(tlo[0], tlo[1]), fminf(tlo[2], tlo[3]));
    hi = fmaxf(fmaxf(thi[0], thi[1]), fmaxf(thi[2], thi[3]));

    const float inv = 1.0f / (hi - lo);
    const int t = blockIdx.x * 128 + tid;
    out[t] = (g_psedu[t] - lo) * inv;
}

// ---------------------------------------------------------------------------
// Launch. Inputs (metadata order): X[8192], weight[128], sigma_min[1],
// sigma_max[1], noise[8192]. Output: float[8192].
// ---------------------------------------------------------------------------
extern "C" void kernel_launch(void* const* d_in, const int* in_sizes, int n_in,
                              void* d_out, int out_size) {
    const float* X     = (const float*)d_in[0];
    const float* wgt   = (const float*)d_in[1];
    const float* smin  = (const float*)d_in[2];
    const float* smax  = (const float*)d_in[3];
    const float* noise = (const float*)d_in[4];
    float* out = (float*)d_out;

    k_gtable<<<NTAPS, 128>>>(wgt, smin, smax);
    k_conv<<<CONV_BLOCKS, 128>>>(X, noise);
    k_norm<<<CONV_BLOCKS, 128>>>(out);
}